// round 1
// baseline (speedup 1.0000x reference)
#include <cuda_runtime.h>
#include <math.h>

// Problem constants
constexpr int kN  = 32768;
constexpr int kC  = 512;
constexpr int kC3 = 1536;
constexpr int kH  = 8;
constexpr int kD  = 64;
constexpr int kW  = 256;
constexpr int kNW = kN / kW;   // 128 windows
constexpr int kSHIFT = 128;
constexpr float kSCALE = 0.125f;  // 1/sqrt(64)

// Scratch (static device arrays — no allocation at runtime)
__device__ float g_qkv[(size_t)kN * kC3];  // 192 MB
__device__ float g_q[(size_t)kN * kC];     // 64 MB (rolled frame)
__device__ float g_k[(size_t)kN * kC];
__device__ float g_v[(size_t)kN * kC];
__device__ float g_h[(size_t)kN * kC];     // attention output, un-rolled frame

// ---------------------------------------------------------------------------
// Tiled fp32 SGEMM with bias: C[M,Nn] = A[M,K] @ B[K,Nn] + bias[Nn]
// BM=128, BN=128, BK=16, 256 threads, 8x8 register tile per thread.
// M % 128 == 0, Nn % 128 == 0, K % 16 == 0 (all true here).
// ---------------------------------------------------------------------------
__global__ void __launch_bounds__(256) sgemm_bias(
    const float* __restrict__ A, const float* __restrict__ B,
    const float* __restrict__ bias, float* __restrict__ C,
    int M, int Nn, int K)
{
    constexpr int BM = 128, BN = 128, BK = 16;
    __shared__ float As[BK][BM];   // transposed A tile
    __shared__ float Bs[BK][BN];

    const int tid = threadIdx.x;
    const int tx = tid & 15;       // 0..15 -> col group
    const int ty = tid >> 4;       // 0..15 -> row group
    const int m0 = blockIdx.y * BM;
    const int n0 = blockIdx.x * BN;

    // A tile load mapping: 128x16 = 512 float4, 2 per thread (same row)
    const int ar = tid >> 1;               // row 0..127
    const int ac = (tid & 1) * 8;          // col 0 or 8
    // B tile load mapping: 16x128 = 512 float4, 2 per thread (contiguous)
    const int br = tid >> 4;               // row 0..15
    const int bc = (tid & 15) * 8;         // col 0..120 step 8

    float acc[8][8];
#pragma unroll
    for (int i = 0; i < 8; i++)
#pragma unroll
        for (int j = 0; j < 8; j++) acc[i][j] = 0.0f;

    for (int k0 = 0; k0 < K; k0 += BK) {
        // load A tile (store transposed into As[k][m])
        float4 a0 = *(const float4*)&A[(size_t)(m0 + ar) * K + k0 + ac];
        float4 a1 = *(const float4*)&A[(size_t)(m0 + ar) * K + k0 + ac + 4];
        As[ac + 0][ar] = a0.x; As[ac + 1][ar] = a0.y;
        As[ac + 2][ar] = a0.z; As[ac + 3][ar] = a0.w;
        As[ac + 4][ar] = a1.x; As[ac + 5][ar] = a1.y;
        As[ac + 6][ar] = a1.z; As[ac + 7][ar] = a1.w;
        // load B tile
        float4 b0 = *(const float4*)&B[(size_t)(k0 + br) * Nn + n0 + bc];
        float4 b1 = *(const float4*)&B[(size_t)(k0 + br) * Nn + n0 + bc + 4];
        *(float4*)&Bs[br][bc]     = b0;
        *(float4*)&Bs[br][bc + 4] = b1;
        __syncthreads();

#pragma unroll
        for (int kk = 0; kk < BK; kk++) {
            float a[8], b[8];
            *(float4*)&a[0] = *(const float4*)&As[kk][ty * 8];
            *(float4*)&a[4] = *(const float4*)&As[kk][ty * 8 + 4];
            *(float4*)&b[0] = *(const float4*)&Bs[kk][tx * 8];
            *(float4*)&b[4] = *(const float4*)&Bs[kk][tx * 8 + 4];
#pragma unroll
            for (int i = 0; i < 8; i++)
#pragma unroll
                for (int j = 0; j < 8; j++)
                    acc[i][j] = fmaf(a[i], b[j], acc[i][j]);
        }
        __syncthreads();
    }

#pragma unroll
    for (int i = 0; i < 8; i++) {
        size_t row = (size_t)(m0 + ty * 8 + i);
#pragma unroll
        for (int j4 = 0; j4 < 2; j4++) {
            int col = n0 + tx * 8 + j4 * 4;
            float4 o;
            o.x = acc[i][j4 * 4 + 0] + bias[col + 0];
            o.y = acc[i][j4 * 4 + 1] + bias[col + 1];
            o.z = acc[i][j4 * 4 + 2] + bias[col + 2];
            o.w = acc[i][j4 * 4 + 3] + bias[col + 3];
            *(float4*)&C[row * Nn + col] = o;
        }
    }
}

// ---------------------------------------------------------------------------
// RoPE + RMS-norm + roll(-128) scatter. One block per token row, 64 threads.
// qkv row layout: [3][H][D] over 1536 cols (q: 0..511, k: 512..1023, v: 1024..)
// ---------------------------------------------------------------------------
__global__ void __launch_bounds__(64) rope_rms_roll(
    const float* __restrict__ qkv, const int* __restrict__ coords,
    const float* __restrict__ gamma_q, const float* __restrict__ gamma_k,
    float* __restrict__ oq, float* __restrict__ ok, float* __restrict__ ov)
{
    const int n = blockIdx.x;
    const int t = threadIdx.x;
    __shared__ float sc[32], ss[32];

    if (t < 32) {
        float theta = 0.0f;
        if (t < 30) {
            int c = t / 10;
            int f = t % 10;
            float freq = 1.0f / powf(10000.0f, (float)f / 10.0f);
            theta = (float)coords[n * 3 + c] * freq;
        }
        sc[t] = cosf(theta);
        ss[t] = sinf(theta);
    }
    __syncthreads();

    const size_t rr = (size_t)((n + kN - kSHIFT) & (kN - 1));  // rolled row
    const size_t qbase = (size_t)n * kC3;

    for (int h = 0; h < kH; h++) {
        // v: plain copy with roll
        ov[rr * kC + h * kD + t] = qkv[qbase + 2 * kC + h * kD + t];

        if (t < 32) {
            const int m = t;
            const float c = sc[m], s = ss[m];
            const int d0 = 2 * m, d1 = 2 * m + 1;

            // q rotate
            float q0 = qkv[qbase + h * kD + d0];
            float q1 = qkv[qbase + h * kD + d1];
            float qr0 = q0 * c - q1 * s;
            float qr1 = q0 * s + q1 * c;
            // k rotate
            float k0 = qkv[qbase + kC + h * kD + d0];
            float k1 = qkv[qbase + kC + h * kD + d1];
            float kr0 = k0 * c - k1 * s;
            float kr1 = k0 * s + k1 * c;

            // warp all-reduce of sum of squares (threads 0..31 = warp 0)
            float sq = qr0 * qr0 + qr1 * qr1;
            float sk = kr0 * kr0 + kr1 * kr1;
#pragma unroll
            for (int off = 16; off > 0; off >>= 1) {
                sq += __shfl_xor_sync(0xffffffffu, sq, off);
                sk += __shfl_xor_sync(0xffffffffu, sk, off);
            }
            float invq = 8.0f * rsqrtf(sq + 1e-12f);  // sqrt(D)=8
            float invk = 8.0f * rsqrtf(sk + 1e-12f);

            oq[rr * kC + h * kD + d0] = qr0 * invq * gamma_q[h * kD + d0];
            oq[rr * kC + h * kD + d1] = qr1 * invq * gamma_q[h * kD + d1];
            ok[rr * kC + h * kD + d0] = kr0 * invk * gamma_k[h * kD + d0];
            ok[rr * kC + h * kD + d1] = kr1 * invk * gamma_k[h * kD + d1];
        }
    }
}

// ---------------------------------------------------------------------------
// Windowed attention. One CTA per (window, head). 256 threads; thread i owns
// query row i. K and V tiles (256x64 fp32 each) staged in 128 KB smem; q row
// and output accumulator live in registers; online softmax.
// Writes h un-rolled: out row = (w*256 + i + 128) mod N.
// ---------------------------------------------------------------------------
__global__ void __launch_bounds__(256, 1) attn_kernel(
    const float* __restrict__ gq, const float* __restrict__ gk,
    const float* __restrict__ gv, float* __restrict__ gh)
{
    extern __shared__ float smem[];
    float* ks = smem;            // 256*64
    float* vs = smem + kW * kD;  // 256*64

    const int w = blockIdx.x;
    const int h = blockIdx.y;
    const int tid = threadIdx.x;

    // cooperative load of K and V tiles (4096 float4 each)
    for (int i = tid; i < (kW * kD) / 4; i += 256) {
        int r = i >> 4;
        int c = i & 15;
        size_t gidx = ((size_t)(w * kW + r)) * kC + h * kD + c * 4;
        ((float4*)ks)[i] = *(const float4*)&gk[gidx];
        ((float4*)vs)[i] = *(const float4*)&gv[gidx];
    }

    // q row into registers
    float qreg[kD];
    {
        const float4* qrow = (const float4*)&gq[((size_t)(w * kW + tid)) * kC + h * kD];
#pragma unroll
        for (int d4 = 0; d4 < 16; d4++) {
            float4 v = qrow[d4];
            qreg[4 * d4 + 0] = v.x; qreg[4 * d4 + 1] = v.y;
            qreg[4 * d4 + 2] = v.z; qreg[4 * d4 + 3] = v.w;
        }
    }
    __syncthreads();

    float acc[kD];
#pragma unroll
    for (int d = 0; d < kD; d++) acc[d] = 0.0f;
    float mmax = -1e30f;
    float lsum = 0.0f;

    for (int j = 0; j < kW; j++) {
        // score = scale * <q_i, k_j>
        const float4* kr = (const float4*)&ks[j * kD];
        float s0 = 0.f, s1 = 0.f, s2 = 0.f, s3 = 0.f;
#pragma unroll
        for (int d4 = 0; d4 < 16; d4++) {
            float4 kv = kr[d4];
            s0 = fmaf(qreg[4 * d4 + 0], kv.x, s0);
            s1 = fmaf(qreg[4 * d4 + 1], kv.y, s1);
            s2 = fmaf(qreg[4 * d4 + 2], kv.z, s2);
            s3 = fmaf(qreg[4 * d4 + 3], kv.w, s3);
        }
        float s = ((s0 + s1) + (s2 + s3)) * kSCALE;

        const float4* vr = (const float4*)&vs[j * kD];
        if (s <= mmax) {
            float p = expf(s - mmax);
            lsum += p;
#pragma unroll
            for (int d4 = 0; d4 < 16; d4++) {
                float4 vv = vr[d4];
                acc[4 * d4 + 0] = fmaf(p, vv.x, acc[4 * d4 + 0]);
                acc[4 * d4 + 1] = fmaf(p, vv.y, acc[4 * d4 + 1]);
                acc[4 * d4 + 2] = fmaf(p, vv.z, acc[4 * d4 + 2]);
                acc[4 * d4 + 3] = fmaf(p, vv.w, acc[4 * d4 + 3]);
            }
        } else {
            float corr = expf(mmax - s);  // 0 on first iteration
            mmax = s;
            lsum = fmaf(lsum, corr, 1.0f);
#pragma unroll
            for (int d4 = 0; d4 < 16; d4++) {
                float4 vv = vr[d4];
                acc[4 * d4 + 0] = fmaf(acc[4 * d4 + 0], corr, vv.x);
                acc[4 * d4 + 1] = fmaf(acc[4 * d4 + 1], corr, vv.y);
                acc[4 * d4 + 2] = fmaf(acc[4 * d4 + 2], corr, vv.z);
                acc[4 * d4 + 3] = fmaf(acc[4 * d4 + 3], corr, vv.w);
            }
        }
    }

    const float inv = 1.0f / lsum;
    const size_t io = (size_t)((w * kW + tid + kSHIFT) & (kN - 1));
    float4* orow = (float4*)&gh[io * kC + h * kD];
#pragma unroll
    for (int d4 = 0; d4 < 16; d4++) {
        float4 o;
        o.x = acc[4 * d4 + 0] * inv;
        o.y = acc[4 * d4 + 1] * inv;
        o.z = acc[4 * d4 + 2] * inv;
        o.w = acc[4 * d4 + 3] * inv;
        orow[d4] = o;
    }
}

// ---------------------------------------------------------------------------
extern "C" void kernel_launch(void* const* d_in, const int* in_sizes, int n_in,
                              void* d_out, int out_size)
{
    const float* x      = (const float*)d_in[0];
    const int*   coords = (const int*)  d_in[1];
    const float* Wqkv   = (const float*)d_in[2];
    const float* b_qkv  = (const float*)d_in[3];
    const float* gamq   = (const float*)d_in[4];
    const float* gamk   = (const float*)d_in[5];
    const float* Wout   = (const float*)d_in[6];
    const float* b_out  = (const float*)d_in[7];
    float* out = (float*)d_out;

    float *pqkv, *pq, *pk, *pv, *ph;
    cudaGetSymbolAddress((void**)&pqkv, g_qkv);
    cudaGetSymbolAddress((void**)&pq,   g_q);
    cudaGetSymbolAddress((void**)&pk,   g_k);
    cudaGetSymbolAddress((void**)&pv,   g_v);
    cudaGetSymbolAddress((void**)&ph,   g_h);

    // 1) qkv = x @ Wqkv + b_qkv
    sgemm_bias<<<dim3(kC3 / 128, kN / 128), 256>>>(x, Wqkv, b_qkv, pqkv, kN, kC3, kC);

    // 2) RoPE + RMS + roll(-128) scatter into q/k/v
    rope_rms_roll<<<kN, 64>>>(pqkv, coords, gamq, gamk, pq, pk, pv);

    // 3) windowed attention (rolled frame), write h back un-rolled
    static const int kAttnSmem = 2 * kW * kD * (int)sizeof(float);  // 128 KB
    cudaFuncSetAttribute(attn_kernel, cudaFuncAttributeMaxDynamicSharedMemorySize, kAttnSmem);
    attn_kernel<<<dim3(kNW, kH), 256, kAttnSmem>>>(pq, pk, pv, ph);

    // 4) out = h @ Wout + b_out
    sgemm_bias<<<dim3(kC / 128, kN / 128), 256>>>(ph, Wout, b_out, out, kN, kC, kC);
}

// round 4
// speedup vs baseline: 1.7101x; 1.7101x over previous
#include <cuda_runtime.h>
#include <math.h>
#include <stdint.h>

// Problem constants
constexpr int kN  = 32768;
constexpr int kC  = 512;
constexpr int kC3 = 1536;
constexpr int kH  = 8;
constexpr int kD  = 64;
constexpr int kW  = 256;
constexpr int kNW = kN / kW;   // 128 windows
constexpr int kSHIFT = 128;
constexpr float kSCALE = 0.125f;  // 1/sqrt(64)

// Scratch (static device arrays — no allocation at runtime)
__device__ float g_qkv[(size_t)kN * kC3];  // 192 MB
__device__ float g_q[(size_t)kN * kC];     // 64 MB (rolled frame)
__device__ float g_k[(size_t)kN * kC];
__device__ float g_v[(size_t)kN * kC];
__device__ float g_h[(size_t)kN * kC];     // attention output, un-rolled frame

__device__ __forceinline__ uint32_t f2tf32(float x) {
    uint32_t r;
    asm("cvt.rna.tf32.f32 %0, %1;" : "=r"(r) : "f"(x));
    return r;
}

// ---------------------------------------------------------------------------
// tf32 tensor-core GEMM with bias: C[M,Nn] = A[M,K] @ B[K,Nn] + bias[Nn]
// BM=128, BN=128, BK=16. 256 threads = 8 warps (2x4), warp tile 64x32.
// mma.sync.aligned.m16n8k8 tf32, cp.async double-buffered smem.
// Requires M%128==0, Nn%128==0, K%16==0.
// ---------------------------------------------------------------------------
__global__ void __launch_bounds__(256, 2) gemm_tf32_bias(
    const float* __restrict__ A, const float* __restrict__ B,
    const float* __restrict__ bias, float* __restrict__ C,
    int M, int Nn, int K)
{
    constexpr int BM = 128, BN = 128, BK = 16;
    constexpr int ASTR = BK + 4;   // 20 floats: banks (m*20+k)%32 conflict-free
    constexpr int BSTR = BN + 8;   // 136 floats: banks (k*136+n)%32 conflict-free

    __shared__ float As[2][BM * ASTR];
    __shared__ float Bs[2][BK * BSTR];

    const int tid  = threadIdx.x;
    const int m0   = blockIdx.y * BM;
    const int n0   = blockIdx.x * BN;
    const int lane = tid & 31;
    const int warp = tid >> 5;
    const int wm   = (warp & 1) * 64;   // warp m-offset
    const int wn   = (warp >> 1) * 32;  // warp n-offset
    const int gr   = lane >> 2;         // group row 0..7
    const int tq   = lane & 3;          // thread-in-group 0..3

    float acc[4][4][4] = {};

    auto loadTiles = [&](int stage, int k0) {
#pragma unroll
        for (int u = 0; u < 2; u++) {
            int c = tid * 2 + u;                 // A chunk id 0..511
            int r = c >> 2, kc = (c & 3) * 4;    // row 0..127, k-chunk
            uint32_t dst = (uint32_t)__cvta_generic_to_shared(&As[stage][r * ASTR + kc]);
            const float* src = A + (size_t)(m0 + r) * K + k0 + kc;
            asm volatile("cp.async.cg.shared.global [%0], [%1], 16;\n" :: "r"(dst), "l"(src));
        }
#pragma unroll
        for (int u = 0; u < 2; u++) {
            int c = tid * 2 + u;                 // B chunk id 0..511
            int r = c >> 5, nc = (c & 31) * 4;   // row 0..15, n-chunk
            uint32_t dst = (uint32_t)__cvta_generic_to_shared(&Bs[stage][r * BSTR + nc]);
            const float* src = B + (size_t)(k0 + r) * Nn + n0 + nc;
            asm volatile("cp.async.cg.shared.global [%0], [%1], 16;\n" :: "r"(dst), "l"(src));
        }
    };

    const int nit = K / BK;
    loadTiles(0, 0);
    asm volatile("cp.async.commit_group;\n" ::: "memory");

    for (int it = 0; it < nit; ++it) {
        if (it + 1 < nit) loadTiles((it + 1) & 1, (it + 1) * BK);
        asm volatile("cp.async.commit_group;\n" ::: "memory");
        asm volatile("cp.async.wait_group 1;\n" ::: "memory");
        __syncthreads();

        const float* as = As[it & 1];
        const float* bs = Bs[it & 1];

#pragma unroll
        for (int ks = 0; ks < 2; ++ks) {
            const int k = ks * 8;
            uint32_t af[4][4], bf[4][2];
#pragma unroll
            for (int im = 0; im < 4; im++) {
                const int mb = wm + im * 16;
                af[im][0] = f2tf32(as[(mb + gr)     * ASTR + k + tq]);
                af[im][1] = f2tf32(as[(mb + gr + 8) * ASTR + k + tq]);
                af[im][2] = f2tf32(as[(mb + gr)     * ASTR + k + tq + 4]);
                af[im][3] = f2tf32(as[(mb + gr + 8) * ASTR + k + tq + 4]);
            }
#pragma unroll
            for (int jn = 0; jn < 4; jn++) {
                const int nb = wn + jn * 8;
                bf[jn][0] = f2tf32(bs[(k + tq)     * BSTR + nb + gr]);
                bf[jn][1] = f2tf32(bs[(k + tq + 4) * BSTR + nb + gr]);
            }
#pragma unroll
            for (int im = 0; im < 4; im++)
#pragma unroll
                for (int jn = 0; jn < 4; jn++) {
                    asm volatile(
                        "mma.sync.aligned.m16n8k8.row.col.f32.tf32.tf32.f32 "
                        "{%0,%1,%2,%3}, {%4,%5,%6,%7}, {%8,%9}, {%0,%1,%2,%3};"
                        : "+f"(acc[im][jn][0]), "+f"(acc[im][jn][1]),
                          "+f"(acc[im][jn][2]), "+f"(acc[im][jn][3])
                        : "r"(af[im][0]), "r"(af[im][1]), "r"(af[im][2]), "r"(af[im][3]),
                          "r"(bf[jn][0]), "r"(bf[jn][1]));
                }
        }
        __syncthreads();
    }

    // Epilogue: c0,c1 at (row, 2tq), (row, 2tq+1); c2,c3 at row+8.
#pragma unroll
    for (int im = 0; im < 4; im++) {
        const int mrow = m0 + wm + im * 16 + gr;
#pragma unroll
        for (int jn = 0; jn < 4; jn++) {
            const int ncol = n0 + wn + jn * 8 + 2 * tq;
            const float b0v = bias[ncol], b1v = bias[ncol + 1];
            float2 o0 = make_float2(acc[im][jn][0] + b0v, acc[im][jn][1] + b1v);
            float2 o1 = make_float2(acc[im][jn][2] + b0v, acc[im][jn][3] + b1v);
            *(float2*)&C[(size_t)mrow       * Nn + ncol] = o0;
            *(float2*)&C[(size_t)(mrow + 8) * Nn + ncol] = o1;
        }
    }
}

// ---------------------------------------------------------------------------
// RoPE + RMS-norm + roll(-128) scatter. One block per token row, 64 threads.
// ---------------------------------------------------------------------------
__global__ void __launch_bounds__(64) rope_rms_roll(
    const float* __restrict__ qkv, const int* __restrict__ coords,
    const float* __restrict__ gamma_q, const float* __restrict__ gamma_k,
    float* __restrict__ oq, float* __restrict__ ok, float* __restrict__ ov)
{
    const int n = blockIdx.x;
    const int t = threadIdx.x;
    __shared__ float sc[32], ss[32];

    if (t < 32) {
        float theta = 0.0f;
        if (t < 30) {
            int c = t / 10;
            int f = t % 10;
            float freq = 1.0f / powf(10000.0f, (float)f / 10.0f);
            theta = (float)coords[n * 3 + c] * freq;
        }
        sc[t] = cosf(theta);
        ss[t] = sinf(theta);
    }
    __syncthreads();

    const size_t rr = (size_t)((n + kN - kSHIFT) & (kN - 1));  // rolled row
    const size_t qbase = (size_t)n * kC3;

    for (int h = 0; h < kH; h++) {
        ov[rr * kC + h * kD + t] = qkv[qbase + 2 * kC + h * kD + t];

        if (t < 32) {
            const int m = t;
            const float c = sc[m], s = ss[m];
            const int d0 = 2 * m, d1 = 2 * m + 1;

            float q0 = qkv[qbase + h * kD + d0];
            float q1 = qkv[qbase + h * kD + d1];
            float qr0 = q0 * c - q1 * s;
            float qr1 = q0 * s + q1 * c;
            float k0 = qkv[qbase + kC + h * kD + d0];
            float k1 = qkv[qbase + kC + h * kD + d1];
            float kr0 = k0 * c - k1 * s;
            float kr1 = k0 * s + k1 * c;

            float sq = qr0 * qr0 + qr1 * qr1;
            float sk = kr0 * kr0 + kr1 * kr1;
#pragma unroll
            for (int off = 16; off > 0; off >>= 1) {
                sq += __shfl_xor_sync(0xffffffffu, sq, off);
                sk += __shfl_xor_sync(0xffffffffu, sk, off);
            }
            float invq = 8.0f * rsqrtf(sq + 1e-12f);
            float invk = 8.0f * rsqrtf(sk + 1e-12f);

            oq[rr * kC + h * kD + d0] = qr0 * invq * gamma_q[h * kD + d0];
            oq[rr * kC + h * kD + d1] = qr1 * invq * gamma_q[h * kD + d1];
            ok[rr * kC + h * kD + d0] = kr0 * invk * gamma_k[h * kD + d0];
            ok[rr * kC + h * kD + d1] = kr1 * invk * gamma_k[h * kD + d1];
        }
    }
}

// ---------------------------------------------------------------------------
// Windowed attention. One CTA per (window, head). 256 threads; thread i owns
// query row i. Online softmax, K/V staged in 128 KB smem.
// ---------------------------------------------------------------------------
__global__ void __launch_bounds__(256, 1) attn_kernel(
    const float* __restrict__ gq, const float* __restrict__ gk,
    const float* __restrict__ gv, float* __restrict__ gh)
{
    extern __shared__ float smem[];
    float* ks = smem;            // 256*64
    float* vs = smem + kW * kD;  // 256*64

    const int w = blockIdx.x;
    const int h = blockIdx.y;
    const int tid = threadIdx.x;

    for (int i = tid; i < (kW * kD) / 4; i += 256) {
        int r = i >> 4;
        int c = i & 15;
        size_t gidx = ((size_t)(w * kW + r)) * kC + h * kD + c * 4;
        ((float4*)ks)[i] = *(const float4*)&gk[gidx];
        ((float4*)vs)[i] = *(const float4*)&gv[gidx];
    }

    float qreg[kD];
    {
        const float4* qrow = (const float4*)&gq[((size_t)(w * kW + tid)) * kC + h * kD];
#pragma unroll
        for (int d4 = 0; d4 < 16; d4++) {
            float4 v = qrow[d4];
            qreg[4 * d4 + 0] = v.x; qreg[4 * d4 + 1] = v.y;
            qreg[4 * d4 + 2] = v.z; qreg[4 * d4 + 3] = v.w;
        }
    }
    __syncthreads();

    float acc[kD];
#pragma unroll
    for (int d = 0; d < kD; d++) acc[d] = 0.0f;
    float mmax = -1e30f;
    float lsum = 0.0f;

    for (int j = 0; j < kW; j++) {
        const float4* kr = (const float4*)&ks[j * kD];
        float s0 = 0.f, s1 = 0.f, s2 = 0.f, s3 = 0.f;
#pragma unroll
        for (int d4 = 0; d4 < 16; d4++) {
            float4 kv = kr[d4];
            s0 = fmaf(qreg[4 * d4 + 0], kv.x, s0);
            s1 = fmaf(qreg[4 * d4 + 1], kv.y, s1);
            s2 = fmaf(qreg[4 * d4 + 2], kv.z, s2);
            s3 = fmaf(qreg[4 * d4 + 3], kv.w, s3);
        }
        float s = ((s0 + s1) + (s2 + s3)) * kSCALE;

        const float4* vr = (const float4*)&vs[j * kD];
        if (s <= mmax) {
            float p = expf(s - mmax);
            lsum += p;
#pragma unroll
            for (int d4 = 0; d4 < 16; d4++) {
                float4 vv = vr[d4];
                acc[4 * d4 + 0] = fmaf(p, vv.x, acc[4 * d4 + 0]);
                acc[4 * d4 + 1] = fmaf(p, vv.y, acc[4 * d4 + 1]);
                acc[4 * d4 + 2] = fmaf(p, vv.z, acc[4 * d4 + 2]);
                acc[4 * d4 + 3] = fmaf(p, vv.w, acc[4 * d4 + 3]);
            }
        } else {
            float corr = expf(mmax - s);
            mmax = s;
            lsum = fmaf(lsum, corr, 1.0f);
#pragma unroll
            for (int d4 = 0; d4 < 16; d4++) {
                float4 vv = vr[d4];
                acc[4 * d4 + 0] = fmaf(acc[4 * d4 + 0], corr, vv.x);
                acc[4 * d4 + 1] = fmaf(acc[4 * d4 + 1], corr, vv.y);
                acc[4 * d4 + 2] = fmaf(acc[4 * d4 + 2], corr, vv.z);
                acc[4 * d4 + 3] = fmaf(acc[4 * d4 + 3], corr, vv.w);
            }
        }
    }

    const float inv = 1.0f / lsum;
    const size_t io = (size_t)((w * kW + tid + kSHIFT) & (kN - 1));
    float4* orow = (float4*)&gh[io * kC + h * kD];
#pragma unroll
    for (int d4 = 0; d4 < 16; d4++) {
        float4 o;
        o.x = acc[4 * d4 + 0] * inv;
        o.y = acc[4 * d4 + 1] * inv;
        o.z = acc[4 * d4 + 2] * inv;
        o.w = acc[4 * d4 + 3] * inv;
        orow[d4] = o;
    }
}

// ---------------------------------------------------------------------------
extern "C" void kernel_launch(void* const* d_in, const int* in_sizes, int n_in,
                              void* d_out, int out_size)
{
    const float* x      = (const float*)d_in[0];
    const int*   coords = (const int*)  d_in[1];
    const float* Wqkv   = (const float*)d_in[2];
    const float* b_qkv  = (const float*)d_in[3];
    const float* gamq   = (const float*)d_in[4];
    const float* gamk   = (const float*)d_in[5];
    const float* Wout   = (const float*)d_in[6];
    const float* b_out  = (const float*)d_in[7];
    float* out = (float*)d_out;

    float *pqkv, *pq, *pk, *pv, *ph;
    cudaGetSymbolAddress((void**)&pqkv, g_qkv);
    cudaGetSymbolAddress((void**)&pq,   g_q);
    cudaGetSymbolAddress((void**)&pk,   g_k);
    cudaGetSymbolAddress((void**)&pv,   g_v);
    cudaGetSymbolAddress((void**)&ph,   g_h);

    // 1) qkv = x @ Wqkv + b_qkv   (tf32 tensor cores)
    gemm_tf32_bias<<<dim3(kC3 / 128, kN / 128), 256>>>(x, Wqkv, b_qkv, pqkv, kN, kC3, kC);

    // 2) RoPE + RMS + roll(-128) scatter into q/k/v
    rope_rms_roll<<<kN, 64>>>(pqkv, coords, gamq, gamk, pq, pk, pv);

    // 3) windowed attention (rolled frame), write h back un-rolled
    static const int kAttnSmem = 2 * kW * kD * (int)sizeof(float);  // 128 KB
    cudaFuncSetAttribute(attn_kernel, cudaFuncAttributeMaxDynamicSharedMemorySize, kAttnSmem);
    attn_kernel<<<dim3(kNW, kH), 256, kAttnSmem>>>(pq, pk, pv, ph);

    // 4) out = h @ Wout + b_out   (tf32 tensor cores)
    gemm_tf32_bias<<<dim3(kC / 128, kN / 128), 256>>>(ph, Wout, b_out, out, kN, kC, kC);
}

// round 7
// speedup vs baseline: 2.4577x; 1.4372x over previous
#include <cuda_runtime.h>
#include <math.h>
#include <stdint.h>

// Problem constants
constexpr int kN  = 32768;
constexpr int kC  = 512;
constexpr int kC3 = 1536;
constexpr int kH  = 8;
constexpr int kD  = 64;
constexpr int kW  = 256;
constexpr int kNW = kN / kW;   // 128 windows
constexpr int kSHIFT = 128;
constexpr float kSCALE = 0.125f;  // 1/sqrt(64)

// Scratch (static device arrays — no allocation at runtime)
__device__ float g_qkv[(size_t)kN * kC3];  // 192 MB
__device__ float g_q[(size_t)kN * kC];     // 64 MB (rolled frame)
__device__ float g_k[(size_t)kN * kC];
__device__ float g_v[(size_t)kN * kC];
__device__ float g_h[(size_t)kN * kC];     // attention output, un-rolled frame

__device__ __forceinline__ uint32_t f2tf32(float x) {
    uint32_t r;
    asm("cvt.rna.tf32.f32 %0, %1;" : "=r"(r) : "f"(x));
    return r;
}

__device__ __forceinline__ void mma_tf32(
    float& c0, float& c1, float& c2, float& c3,
    uint32_t a0, uint32_t a1, uint32_t a2, uint32_t a3,
    uint32_t b0, uint32_t b1)
{
    asm volatile(
        "mma.sync.aligned.m16n8k8.row.col.f32.tf32.tf32.f32 "
        "{%0,%1,%2,%3}, {%4,%5,%6,%7}, {%8,%9}, {%0,%1,%2,%3};"
        : "+f"(c0), "+f"(c1), "+f"(c2), "+f"(c3)
        : "r"(a0), "r"(a1), "r"(a2), "r"(a3), "r"(b0), "r"(b1));
}

// ---------------------------------------------------------------------------
// tf32 tensor-core GEMM with bias: C[M,Nn] = A[M,K] @ B[K,Nn] + bias[Nn]
// (unchanged from round 4 — validated)
// ---------------------------------------------------------------------------
__global__ void __launch_bounds__(256, 2) gemm_tf32_bias(
    const float* __restrict__ A, const float* __restrict__ B,
    const float* __restrict__ bias, float* __restrict__ C,
    int M, int Nn, int K)
{
    constexpr int BM = 128, BN = 128, BK = 16;
    constexpr int ASTR = BK + 4;
    constexpr int BSTR = BN + 8;

    __shared__ float As[2][BM * ASTR];
    __shared__ float Bs[2][BK * BSTR];

    const int tid  = threadIdx.x;
    const int m0   = blockIdx.y * BM;
    const int n0   = blockIdx.x * BN;
    const int lane = tid & 31;
    const int warp = tid >> 5;
    const int wm   = (warp & 1) * 64;
    const int wn   = (warp >> 1) * 32;
    const int gr   = lane >> 2;
    const int tq   = lane & 3;

    float acc[4][4][4] = {};

    auto loadTiles = [&](int stage, int k0) {
#pragma unroll
        for (int u = 0; u < 2; u++) {
            int c = tid * 2 + u;
            int r = c >> 2, kc = (c & 3) * 4;
            uint32_t dst = (uint32_t)__cvta_generic_to_shared(&As[stage][r * ASTR + kc]);
            const float* src = A + (size_t)(m0 + r) * K + k0 + kc;
            asm volatile("cp.async.cg.shared.global [%0], [%1], 16;\n" :: "r"(dst), "l"(src));
        }
#pragma unroll
        for (int u = 0; u < 2; u++) {
            int c = tid * 2 + u;
            int r = c >> 5, nc = (c & 31) * 4;
            uint32_t dst = (uint32_t)__cvta_generic_to_shared(&Bs[stage][r * BSTR + nc]);
            const float* src = B + (size_t)(k0 + r) * Nn + n0 + nc;
            asm volatile("cp.async.cg.shared.global [%0], [%1], 16;\n" :: "r"(dst), "l"(src));
        }
    };

    const int nit = K / BK;
    loadTiles(0, 0);
    asm volatile("cp.async.commit_group;\n" ::: "memory");

    for (int it = 0; it < nit; ++it) {
        if (it + 1 < nit) loadTiles((it + 1) & 1, (it + 1) * BK);
        asm volatile("cp.async.commit_group;\n" ::: "memory");
        asm volatile("cp.async.wait_group 1;\n" ::: "memory");
        __syncthreads();

        const float* as = As[it & 1];
        const float* bs = Bs[it & 1];

#pragma unroll
        for (int ks = 0; ks < 2; ++ks) {
            const int k = ks * 8;
            uint32_t af[4][4], bf[4][2];
#pragma unroll
            for (int im = 0; im < 4; im++) {
                const int mb = wm + im * 16;
                af[im][0] = f2tf32(as[(mb + gr)     * ASTR + k + tq]);
                af[im][1] = f2tf32(as[(mb + gr + 8) * ASTR + k + tq]);
                af[im][2] = f2tf32(as[(mb + gr)     * ASTR + k + tq + 4]);
                af[im][3] = f2tf32(as[(mb + gr + 8) * ASTR + k + tq + 4]);
            }
#pragma unroll
            for (int jn = 0; jn < 4; jn++) {
                const int nb = wn + jn * 8;
                bf[jn][0] = f2tf32(bs[(k + tq)     * BSTR + nb + gr]);
                bf[jn][1] = f2tf32(bs[(k + tq + 4) * BSTR + nb + gr]);
            }
#pragma unroll
            for (int im = 0; im < 4; im++)
#pragma unroll
                for (int jn = 0; jn < 4; jn++)
                    mma_tf32(acc[im][jn][0], acc[im][jn][1], acc[im][jn][2], acc[im][jn][3],
                             af[im][0], af[im][1], af[im][2], af[im][3],
                             bf[jn][0], bf[jn][1]);
        }
        __syncthreads();
    }

#pragma unroll
    for (int im = 0; im < 4; im++) {
        const int mrow = m0 + wm + im * 16 + gr;
#pragma unroll
        for (int jn = 0; jn < 4; jn++) {
            const int ncol = n0 + wn + jn * 8 + 2 * tq;
            const float b0v = bias[ncol], b1v = bias[ncol + 1];
            float2 o0 = make_float2(acc[im][jn][0] + b0v, acc[im][jn][1] + b1v);
            float2 o1 = make_float2(acc[im][jn][2] + b0v, acc[im][jn][3] + b1v);
            *(float2*)&C[(size_t)mrow       * Nn + ncol] = o0;
            *(float2*)&C[(size_t)(mrow + 8) * Nn + ncol] = o1;
        }
    }
}

// ---------------------------------------------------------------------------
// RoPE + RMS-norm + roll(-128) scatter. (unchanged)
// ---------------------------------------------------------------------------
__global__ void __launch_bounds__(64) rope_rms_roll(
    const float* __restrict__ qkv, const int* __restrict__ coords,
    const float* __restrict__ gamma_q, const float* __restrict__ gamma_k,
    float* __restrict__ oq, float* __restrict__ ok, float* __restrict__ ov)
{
    const int n = blockIdx.x;
    const int t = threadIdx.x;
    __shared__ float sc[32], ss[32];

    if (t < 32) {
        float theta = 0.0f;
        if (t < 30) {
            int c = t / 10;
            int f = t % 10;
            float freq = 1.0f / powf(10000.0f, (float)f / 10.0f);
            theta = (float)coords[n * 3 + c] * freq;
        }
        sc[t] = cosf(theta);
        ss[t] = sinf(theta);
    }
    __syncthreads();

    const size_t rr = (size_t)((n + kN - kSHIFT) & (kN - 1));
    const size_t qbase = (size_t)n * kC3;

    for (int h = 0; h < kH; h++) {
        ov[rr * kC + h * kD + t] = qkv[qbase + 2 * kC + h * kD + t];

        if (t < 32) {
            const int m = t;
            const float c = sc[m], s = ss[m];
            const int d0 = 2 * m, d1 = 2 * m + 1;

            float q0 = qkv[qbase + h * kD + d0];
            float q1 = qkv[qbase + h * kD + d1];
            float qr0 = q0 * c - q1 * s;
            float qr1 = q0 * s + q1 * c;
            float k0 = qkv[qbase + kC + h * kD + d0];
            float k1 = qkv[qbase + kC + h * kD + d1];
            float kr0 = k0 * c - k1 * s;
            float kr1 = k0 * s + k1 * c;

            float sq = qr0 * qr0 + qr1 * qr1;
            float sk = kr0 * kr0 + kr1 * kr1;
#pragma unroll
            for (int off = 16; off > 0; off >>= 1) {
                sq += __shfl_xor_sync(0xffffffffu, sq, off);
                sk += __shfl_xor_sync(0xffffffffu, sk, off);
            }
            float invq = 8.0f * rsqrtf(sq + 1e-12f);
            float invk = 8.0f * rsqrtf(sk + 1e-12f);

            oq[rr * kC + h * kD + d0] = qr0 * invq * gamma_q[h * kD + d0];
            oq[rr * kC + h * kD + d1] = qr1 * invq * gamma_q[h * kD + d1];
            ok[rr * kC + h * kD + d0] = kr0 * invk * gamma_k[h * kD + d0];
            ok[rr * kC + h * kD + d1] = kr1 * invk * gamma_k[h * kD + d1];
        }
    }
}

// ---------------------------------------------------------------------------
// Tensor-core windowed attention. One CTA per (window, head), 256 thr / 8 warps.
// smem: K[256][68], V^T[64][260], S[64][260], Q[64][68], rowsum[64]  (~215 KB)
// Loop over 4 q-blocks of 64 rows:
//   S = Q K^T (tf32 MMA, warp n-slice 32) -> smem
//   softmax rows (warp per 8 rows, __expf, deferred 1/sum)
//   O = P V (tf32 MMA, warp tile 16x32, K=256) -> gmem (rolled +128)
// ---------------------------------------------------------------------------
constexpr int KSTR = 68;    // K,Q smem stride: 68%32=4 -> banks 4*gr+tq distinct
constexpr int SSTR = 260;   // S,VT smem stride: 260%32=4 -> conflict-free
constexpr int kAttnSmemFloats = kW * KSTR + kD * SSTR + 64 * SSTR + 64 * KSTR + 64;

__global__ void __launch_bounds__(256, 1) attn_tc_kernel(
    const float* __restrict__ gq, const float* __restrict__ gk,
    const float* __restrict__ gv, float* __restrict__ gh)
{
    extern __shared__ float smem[];
    float* Ks = smem;                    // 256*68
    float* VT = Ks + kW * KSTR;          // 64*260 (V transposed: VT[d][kv])
    float* Ss = VT + kD * SSTR;          // 64*260
    float* Qs = Ss + 64 * SSTR;          // 64*68
    float* rs = Qs + 64 * KSTR;          // 64 row sums

    const int w   = blockIdx.x;
    const int h   = blockIdx.y;
    const int tid = threadIdx.x;
    const int lane = tid & 31;
    const int warp = tid >> 5;
    const int gr = lane >> 2;   // 0..7
    const int tq = lane & 3;    // 0..3

    // ---- load K and V^T (coalesced 16-lane rows) ----
    for (int i = tid; i < (kW * kD) / 4; i += 256) {
        int r = i >> 4;          // kv row 0..255
        int c4 = (i & 15) * 4;   // d offset
        size_t gidx = ((size_t)(w * kW + r)) * kC + h * kD + c4;
        float4 kv4 = *(const float4*)&gk[gidx];
        *(float4*)&Ks[r * KSTR + c4] = kv4;
        float4 vv4 = *(const float4*)&gv[gidx];
        VT[(c4 + 0) * SSTR + r] = vv4.x;
        VT[(c4 + 1) * SSTR + r] = vv4.y;
        VT[(c4 + 2) * SSTR + r] = vv4.z;
        VT[(c4 + 3) * SSTR + r] = vv4.w;
    }

    for (int qb = 0; qb < 4; qb++) {
        __syncthreads();
        // ---- load Q block (64 rows) ----
        for (int i = tid; i < (64 * kD) / 4; i += 256) {
            int r = i >> 4;
            int c4 = (i & 15) * 4;
            size_t gidx = ((size_t)(w * kW + qb * 64 + r)) * kC + h * kD + c4;
            *(float4*)&Qs[r * KSTR + c4] = *(const float4*)&gq[gidx];
        }
        __syncthreads();

        // ---- phase 1: S = Q K^T, warp owns n-slice [warp*32, warp*32+32) ----
        {
            const int wn = warp * 32;
            float acc[4][4][4] = {};
#pragma unroll
            for (int ks = 0; ks < 8; ks++) {
                const int k = ks * 8;
                uint32_t af[4][4], bf[4][2];
#pragma unroll
                for (int im = 0; im < 4; im++) {
                    const int mb = im * 16;
                    af[im][0] = f2tf32(Qs[(mb + gr)     * KSTR + k + tq]);
                    af[im][1] = f2tf32(Qs[(mb + gr + 8) * KSTR + k + tq]);
                    af[im][2] = f2tf32(Qs[(mb + gr)     * KSTR + k + tq + 4]);
                    af[im][3] = f2tf32(Qs[(mb + gr + 8) * KSTR + k + tq + 4]);
                }
#pragma unroll
                for (int jn = 0; jn < 4; jn++) {
                    const int nb = wn + jn * 8;
                    bf[jn][0] = f2tf32(Ks[(nb + gr) * KSTR + k + tq]);
                    bf[jn][1] = f2tf32(Ks[(nb + gr) * KSTR + k + tq + 4]);
                }
#pragma unroll
                for (int im = 0; im < 4; im++)
#pragma unroll
                    for (int jn = 0; jn < 4; jn++)
                        mma_tf32(acc[im][jn][0], acc[im][jn][1], acc[im][jn][2], acc[im][jn][3],
                                 af[im][0], af[im][1], af[im][2], af[im][3],
                                 bf[jn][0], bf[jn][1]);
            }
            // write S * scale
#pragma unroll
            for (int im = 0; im < 4; im++) {
                const int r0 = im * 16 + gr;
#pragma unroll
                for (int jn = 0; jn < 4; jn++) {
                    const int c = wn + jn * 8 + 2 * tq;
                    *(float2*)&Ss[r0 * SSTR + c] =
                        make_float2(acc[im][jn][0] * kSCALE, acc[im][jn][1] * kSCALE);
                    *(float2*)&Ss[(r0 + 8) * SSTR + c] =
                        make_float2(acc[im][jn][2] * kSCALE, acc[im][jn][3] * kSCALE);
                }
            }
        }
        __syncthreads();

        // ---- phase 2: softmax (warp handles rows warp*8..warp*8+7) ----
        for (int rr = 0; rr < 8; rr++) {
            const int r = warp * 8 + rr;
            float v[8];
            float m = -1e30f;
#pragma unroll
            for (int i = 0; i < 8; i++) {
                v[i] = Ss[r * SSTR + lane + 32 * i];
                m = fmaxf(m, v[i]);
            }
#pragma unroll
            for (int off = 16; off > 0; off >>= 1)
                m = fmaxf(m, __shfl_xor_sync(0xffffffffu, m, off));
            float sum = 0.0f;
#pragma unroll
            for (int i = 0; i < 8; i++) {
                v[i] = __expf(v[i] - m);
                sum += v[i];
                Ss[r * SSTR + lane + 32 * i] = v[i];
            }
#pragma unroll
            for (int off = 16; off > 0; off >>= 1)
                sum += __shfl_xor_sync(0xffffffffu, sum, off);
            if (lane == 0) rs[r] = sum;
        }
        __syncthreads();

        // ---- phase 3: O = P V  (M=64 N=64 K=256; warp tile 16x32) ----
        {
            const int wm  = (warp >> 1) * 16;
            const int wn2 = (warp & 1) * 32;
            float acc[4][4] = {};
#pragma unroll
            for (int ks = 0; ks < 32; ks++) {
                const int k = ks * 8;
                uint32_t af[4], bf[4][2];
                af[0] = f2tf32(Ss[(wm + gr)     * SSTR + k + tq]);
                af[1] = f2tf32(Ss[(wm + gr + 8) * SSTR + k + tq]);
                af[2] = f2tf32(Ss[(wm + gr)     * SSTR + k + tq + 4]);
                af[3] = f2tf32(Ss[(wm + gr + 8) * SSTR + k + tq + 4]);
#pragma unroll
                for (int jn = 0; jn < 4; jn++) {
                    const int nb = wn2 + jn * 8;
                    bf[jn][0] = f2tf32(VT[(nb + gr) * SSTR + k + tq]);
                    bf[jn][1] = f2tf32(VT[(nb + gr) * SSTR + k + tq + 4]);
                }
#pragma unroll
                for (int jn = 0; jn < 4; jn++)
                    mma_tf32(acc[jn][0], acc[jn][1], acc[jn][2], acc[jn][3],
                             af[0], af[1], af[2], af[3], bf[jn][0], bf[jn][1]);
            }
            // store O (rolled +SHIFT), scale by 1/rowsum
            const float inv0 = 1.0f / rs[wm + gr];
            const float inv1 = 1.0f / rs[wm + gr + 8];
            const int q0 = w * kW + qb * 64 + wm + gr;
            const size_t io0 = (size_t)((q0 + kSHIFT) & (kN - 1));
            const size_t io1 = (size_t)((q0 + 8 + kSHIFT) & (kN - 1));
#pragma unroll
            for (int jn = 0; jn < 4; jn++) {
                const int c = h * kD + wn2 + jn * 8 + 2 * tq;
                *(float2*)&gh[io0 * kC + c] =
                    make_float2(acc[jn][0] * inv0, acc[jn][1] * inv0);
                *(float2*)&gh[io1 * kC + c] =
                    make_float2(acc[jn][2] * inv1, acc[jn][3] * inv1);
            }
        }
    }
}

// ---------------------------------------------------------------------------
extern "C" void kernel_launch(void* const* d_in, const int* in_sizes, int n_in,
                              void* d_out, int out_size)
{
    const float* x      = (const float*)d_in[0];
    const int*   coords = (const int*)  d_in[1];
    const float* Wqkv   = (const float*)d_in[2];
    const float* b_qkv  = (const float*)d_in[3];
    const float* gamq   = (const float*)d_in[4];
    const float* gamk   = (const float*)d_in[5];
    const float* Wout   = (const float*)d_in[6];
    const float* b_out  = (const float*)d_in[7];
    float* out = (float*)d_out;

    float *pqkv, *pq, *pk, *pv, *ph;
    cudaGetSymbolAddress((void**)&pqkv, g_qkv);
    cudaGetSymbolAddress((void**)&pq,   g_q);
    cudaGetSymbolAddress((void**)&pk,   g_k);
    cudaGetSymbolAddress((void**)&pv,   g_v);
    cudaGetSymbolAddress((void**)&ph,   g_h);

    // 1) qkv = x @ Wqkv + b_qkv   (tf32 tensor cores)
    gemm_tf32_bias<<<dim3(kC3 / 128, kN / 128), 256>>>(x, Wqkv, b_qkv, pqkv, kN, kC3, kC);

    // 2) RoPE + RMS + roll(-128) scatter into q/k/v
    rope_rms_roll<<<kN, 64>>>(pqkv, coords, gamq, gamk, pq, pk, pv);

    // 3) tensor-core windowed attention
    static const int kAttnSmem = kAttnSmemFloats * (int)sizeof(float);  // ~215 KB
    cudaFuncSetAttribute(attn_tc_kernel, cudaFuncAttributeMaxDynamicSharedMemorySize, kAttnSmem);
    attn_tc_kernel<<<dim3(kNW, kH), 256, kAttnSmem>>>(pq, pk, pv, ph);

    // 4) out = h @ Wout + b_out   (tf32 tensor cores)
    gemm_tf32_bias<<<dim3(kC / 128, kN / 128), 256>>>(ph, Wout, b_out, out, kN, kC, kC);
}